// round 3
// baseline (speedup 1.0000x reference)
#include <cuda_runtime.h>
#include <math.h>
#include <stdint.h>

#define MM   5000
#define EE   128
#define DD   512
#define DII  2048
#define HH   8
#define CC   256
#define SS   32
#define BB   32
#define TT   64
#define TMS  63
#define LP   1954
#define LNN  2017

// ---------------- device scratch ----------------
__device__ int   g_cand[CC];
__device__ float g_At[EE * CC];          // A transposed: [e][c]
__device__ float g_Bm[MM * EE];
__device__ int   g_nlist[MM * SS];
__device__ float g_nprob[MM * SS];
__device__ float g_kc[BB * TMS * DD];    // [b][t][h*64+d]
__device__ float g_vc[BB * TMS * DD];

// ---------------- threefry2x32 (JAX partitionable semantics) ----------------
__device__ __forceinline__ void tf2x32(uint32_t k0, uint32_t k1,
                                       uint32_t x0, uint32_t x1,
                                       uint32_t& o0, uint32_t& o1) {
    uint32_t k2 = k0 ^ k1 ^ 0x1BD11BDAu;
    x0 += k0; x1 += k1;
#define TF_R(r) { x0 += x1; x1 = (x1 << r) | (x1 >> (32 - r)); x1 ^= x0; }
    TF_R(13) TF_R(15) TF_R(26) TF_R(6)   x0 += k1; x1 += k2 + 1u;
    TF_R(17) TF_R(29) TF_R(16) TF_R(24)  x0 += k2; x1 += k0 + 2u;
    TF_R(13) TF_R(15) TF_R(26) TF_R(6)   x0 += k0; x1 += k1 + 3u;
    TF_R(17) TF_R(29) TF_R(16) TF_R(24)  x0 += k1; x1 += k2 + 4u;
    TF_R(13) TF_R(15) TF_R(26) TF_R(6)   x0 += k2; x1 += k0 + 5u;
#undef TF_R
    o0 = x0; o1 = x1;
}

__device__ __forceinline__ uint32_t rbits(uint32_t k0, uint32_t k1, uint32_t idx) {
    uint32_t a, b;
    tf2x32(k0, k1, 0u, idx, a, b);
    return a ^ b;
}

__device__ __forceinline__ float gumbel_u32(uint32_t bits) {
    const float tiny = 1.17549435e-38f;
    float f = __uint_as_float((bits >> 9) | 0x3f800000u) - 1.0f;  // [0,1)
    float u = f + tiny;                // floats*(1-tiny)+tiny, (1-tiny)==1.0f
    u = fmaxf(tiny, u);
    return -logf(-logf(u));
}

// ---------------- block reductions ----------------
__device__ __forceinline__ float blockSum(float v, float* rs) {
    int tid = threadIdx.x, w = tid >> 5, l = tid & 31, nw = blockDim.x >> 5;
#pragma unroll
    for (int o = 16; o > 0; o >>= 1) v += __shfl_xor_sync(0xffffffffu, v, o);
    if (l == 0) rs[w] = v;
    __syncthreads();
    if (w == 0) {
        float x = (l < nw) ? rs[l] : 0.0f;
#pragma unroll
        for (int o = 16; o > 0; o >>= 1) x += __shfl_xor_sync(0xffffffffu, x, o);
        if (l == 0) rs[0] = x;
    }
    __syncthreads();
    float r = rs[0];
    __syncthreads();
    return r;
}

__device__ __forceinline__ float blockMax(float v, float* rs) {
    int tid = threadIdx.x, w = tid >> 5, l = tid & 31, nw = blockDim.x >> 5;
#pragma unroll
    for (int o = 16; o > 0; o >>= 1) v = fmaxf(v, __shfl_xor_sync(0xffffffffu, v, o));
    if (l == 0) rs[w] = v;
    __syncthreads();
    if (w == 0) {
        float x = (l < nw) ? rs[l] : -INFINITY;
#pragma unroll
        for (int o = 16; o > 0; o >>= 1) x = fmaxf(x, __shfl_xor_sync(0xffffffffu, x, o));
        if (l == 0) rs[0] = x;
    }
    __syncthreads();
    float r = rs[0];
    __syncthreads();
    return r;
}

__device__ __forceinline__ void warpArgmax(float& v, int& idx) {
#pragma unroll
    for (int o = 16; o > 0; o >>= 1) {
        float ov = __shfl_xor_sync(0xffffffffu, v, o);
        int   oi = __shfl_xor_sync(0xffffffffu, idx, o);
        if (ov > v || (ov == v && oi < idx)) { v = ov; idx = oi; }
    }
}

// tie -> lowest index (matches lax.top_k / argmax)
__device__ __forceinline__ void blockArgmax(float& v, int& idx, float* rv, int* ri) {
    int tid = threadIdx.x, w = tid >> 5, l = tid & 31, nw = (blockDim.x + 31) >> 5;
    warpArgmax(v, idx);
    if (l == 0) { rv[w] = v; ri[w] = idx; }
    __syncthreads();
    if (w == 0) {
        float vv = (l < nw) ? rv[l] : -INFINITY;
        int   ii = (l < nw) ? ri[l] : 0x7fffffff;
        warpArgmax(vv, ii);
        if (l == 0) { rv[0] = vv; ri[0] = ii; }
    }
    __syncthreads();
    v = rv[0]; idx = ri[0];
    __syncthreads();
}

// ---------------- kernel 1: gumbel(k1,(M,)) top-256 -> g_cand ----------------
__global__ void __launch_bounds__(1024) k_topk_cand() {
    __shared__ float vals[MM];
    __shared__ float rv[32];
    __shared__ int   ri[32];
    uint32_t ka, kb;                    // k1 = split(key(7))[0] = TF((0,7),(0,0))
    tf2x32(0u, 7u, 0u, 0u, ka, kb);
    for (int i = threadIdx.x; i < MM; i += blockDim.x)
        vals[i] = gumbel_u32(rbits(ka, kb, (uint32_t)i));
    __syncthreads();
    for (int r = 0; r < CC; r++) {
        float bv = -INFINITY; int bi = 0x7fffffff;
        for (int i = threadIdx.x; i < MM; i += blockDim.x) {
            float v = vals[i];
            if (v > bv) { bv = v; bi = i; }
        }
        blockArgmax(bv, bi, rv, ri);
        if (threadIdx.x == 0) { g_cand[r] = bi; vals[bi] = -INFINITY; }
        __syncthreads();
    }
}

// ---------------- kernel 2: Bm = emb @ s1_w[E:] ----------------
__global__ void __launch_bounds__(EE) k_bm(const float* __restrict__ emb,
                                           const float* __restrict__ s1w) {
    __shared__ float se[EE];
    int m = blockIdx.x, d = threadIdx.x;
    se[d] = emb[m * EE + d];
    __syncthreads();
    float acc = 0.0f;
#pragma unroll 8
    for (int e = 0; e < EE; e++) acc += se[e] * s1w[(EE + e) * EE + d];
    g_Bm[m * EE + d] = acc;
}

// ---------------- kernel 3: At = (emb[cand] @ s1_w[:E])^T ----------------
__global__ void __launch_bounds__(EE) k_a(const float* __restrict__ emb,
                                          const float* __restrict__ s1w) {
    __shared__ float se[EE];
    int c = blockIdx.x, d = threadIdx.x;
    int mm = g_cand[c];
    se[d] = emb[mm * EE + d];
    __syncthreads();
    float acc = 0.0f;
#pragma unroll 8
    for (int e = 0; e < EE; e++) acc += se[e] * s1w[e * EE + d];
    g_At[d * CC + c] = acc;
}

// ---------------- kernel 4: softmax over 256 cand + gumbel top-32 ----------------
__global__ void __launch_bounds__(CC) k_select(const float* __restrict__ s1b,
                                               const float* __restrict__ s2w,
                                               const float* __restrict__ s2b) {
    __shared__ float sb[EE], sw[EE], sbm[EE];
    __shared__ float p[CC], sc[CC];
    __shared__ float rs[32];
    __shared__ float rv[32];
    __shared__ int   ri[32];
    int m = blockIdx.x, c = threadIdx.x;
    if (c < EE) { sb[c] = s1b[c]; sw[c] = s2w[c]; sbm[c] = g_Bm[m * EE + c]; }
    __syncthreads();
    float acc = 0.0f;
#pragma unroll 4
    for (int e = 0; e < EE; e++) {
        float t = g_At[e * CC + c] + sbm[e] + sb[e];
        t = (t >= 0.0f) ? t : 0.01f * t;
        acc += t * sw[e];
    }
    float logit = acc + s2b[0];
    float mx = blockMax(logit, rs);
    float ex = expf(logit - mx);
    float sm = blockSum(ex, rs);
    float pc = ex / sm;
    p[c] = pc;
    uint32_t ka, kb;                    // k2 = split(key(7))[1] = TF((0,7),(0,1))
    tf2x32(0u, 7u, 0u, 1u, ka, kb);
    sc[c] = logf(pc) + gumbel_u32(rbits(ka, kb, (uint32_t)(m * CC + c)));
    __syncthreads();
    for (int s = 0; s < SS; s++) {
        float bv = sc[c]; int bi = c;
        blockArgmax(bv, bi, rv, ri);
        if (threadIdx.x == 0) {
            g_nlist[m * SS + s] = g_cand[bi];
            g_nprob[m * SS + s] = p[bi];
            sc[bi] = -INFINITY;
        }
        __syncthreads();
    }
}

// ---------------- kernel 5: the 63-step scan, one block per batch row ----------------
__global__ void __launch_bounds__(1024) k_seq(
    const int*   __restrict__ marker_data, const float* __restrict__ time_data,
    const float* __restrict__ mask_data,   const float* __restrict__ emb,
    const float* __restrict__ te_w, const float* __restrict__ te_b,
    const float* __restrict__ el_w, const float* __restrict__ el_b,
    const float* __restrict__ ml_w, const float* __restrict__ ml_b,
    const float* __restrict__ tl_w, const float* __restrict__ tl_b,
    const float* __restrict__ wq,   const float* __restrict__ wk,
    const float* __restrict__ wv,   const float* __restrict__ wo,
    const float* __restrict__ wo_b,
    const float* __restrict__ ln1_s, const float* __restrict__ ln1_b,
    const float* __restrict__ ff1_w, const float* __restrict__ ff1_b,
    const float* __restrict__ ff2_w, const float* __restrict__ ff2_b,
    const float* __restrict__ ln2_s, const float* __restrict__ ln2_b,
    float* __restrict__ out)
{
    const int b = blockIdx.x, tid = threadIdx.x;

    __shared__ float s_prob[LP];
    __shared__ int   s_cand[LP];
    __shared__ float s_nrec[LNN];
    __shared__ float s_h1[DII];
    __shared__ float s_md[DD], s_q[DD], s_x1[DD], s_int[DD], s_ctx[DD];
    __shared__ float s_sc[HH * 64];
    __shared__ float s_part[DD];
    __shared__ float s_vvec[EE];
    __shared__ float s_mw[SS];
    __shared__ int   s_nb[SS];
    __shared__ float rs[32];
    __shared__ float rv[32];
    __shared__ int   ri[32];
    __shared__ float sv_lt;
    __shared__ int   sv_lm, sv_chosen;

    for (int j = tid; j < LP;  j += 1024) { s_prob[j] = 0.0f; s_cand[j] = 0; }
    for (int j = tid; j < LNN; j += 1024) s_nrec[j] = 0.0f;
    if (tid == 0) {
        int   m0 = marker_data[b * TT];
        float t0 = time_data[b * TT];
        s_prob[0] = 1.0f; s_cand[0] = m0; s_nrec[0] = 1.0f;
        sv_lm = m0; sv_lt = t0; sv_chosen = 0;
        out[0 * (BB * TT) + b * TT] = (float)m0;
        out[1 * (BB * TT) + b * TT] = t0;
        out[2 * (BB * TT) + b * TT] = mask_data[b * TT];
        out[3 * (BB * TT) + b * TT] = 1.0f;
        out[4 * (BB * TT) + b * TT] = 1.0f;
    }
    __syncthreads();

    for (int i = 0; i < TMS; i++) {
        const int   lm = sv_lm;
        const float lt = sv_lt;
        const int   chosen = sv_chosen;

        // ---- vvec = emb[lm] + 0.1*(lt*te_w + te_b) ----
        if (tid < EE) s_vvec[tid] = emb[lm * EE + tid] + 0.1f * (lt * te_w[tid] + te_b[tid]);
        __syncthreads();

        // ---- md = lrelu(vvec @ el_w + el_b) ----
        if (tid < DD) {
            float acc = 0.0f;
#pragma unroll 8
            for (int e = 0; e < EE; e++) acc += s_vvec[e] * el_w[e * DD + tid];
            acc += el_b[tid];
            s_md[tid] = (acc >= 0.0f) ? acc : 0.01f * acc;
        }
        __syncthreads();

        // ---- q, k, v GEMVs ----
        {
            if (tid < DD) {
                float acc = 0.0f;
#pragma unroll 4
                for (int e = 0; e < DD; e++) acc += s_md[e] * wq[e * DD + tid];
                s_q[tid] = acc;
            } else {
                int d = tid - DD;
                float acc = 0.0f;
#pragma unroll 4
                for (int e = 0; e < DD; e++) acc += s_md[e] * wk[e * DD + d];
                g_kc[(b * TMS + i) * DD + d] = acc;
            }
            if (tid < DD) {
                float acc = 0.0f;
#pragma unroll 4
                for (int e = 0; e < DD; e++) acc += s_md[e] * wv[e * DD + tid];
                g_vc[(b * TMS + i) * DD + tid] = acc;
            }
        }
        __syncthreads();

        // ---- attention scores: sc[h][t] = 0.125 * q[h].k[t,h], t<=i ----
        if (tid < HH * (i + 1)) {
            int t = tid >> 3, h = tid & 7;
            float acc = 0.0f;
            const float* kp = &g_kc[(b * TMS + t) * DD + h * 64];
            const float* qp = &s_q[h * 64];
#pragma unroll 8
            for (int d = 0; d < 64; d++) acc += qp[d] * kp[d];
            s_sc[h * 64 + t] = acc * 0.125f;
        }
        __syncthreads();

        // ---- per-head softmax over t<=i (in place) ----
        if (tid < HH) {
            int h = tid;
            float mx = -INFINITY;
            for (int t = 0; t <= i; t++) mx = fmaxf(mx, s_sc[h * 64 + t]);
            float sm = 0.0f;
            for (int t = 0; t <= i; t++) { float e = expf(s_sc[h * 64 + t] - mx); s_sc[h * 64 + t] = e; sm += e; }
            for (int t = 0; t <= i; t++) s_sc[h * 64 + t] /= sm;
        }
        __syncthreads();

        // ---- ctx[c] = sum_t p[h,t]*v[t,c] ----
        if (tid < DD) {
            int h = tid >> 6;
            float acc = 0.0f;
            for (int t = 0; t <= i; t++) acc += s_sc[h * 64 + t] * g_vc[(b * TMS + t) * DD + tid];
            s_ctx[tid] = acc;
        }
        __syncthreads();

        // ---- x1 = LN1(md + ctx@wo + wo_b) ----
        {
            float val = 0.0f;
            if (tid < DD) {
                float acc = 0.0f;
#pragma unroll 4
                for (int c = 0; c < DD; c++) acc += s_ctx[c] * wo[c * DD + tid];
                val = s_md[tid] + acc + wo_b[tid];
            }
            float mean = blockSum(tid < DD ? val : 0.0f, rs) / (float)DD;
            float dv = (tid < DD) ? (val - mean) : 0.0f;
            float var = blockSum(dv * dv, rs) / (float)DD;
            if (tid < DD) s_x1[tid] = dv / sqrtf(var + 1e-5f) * ln1_s[tid] + ln1_b[tid];
        }
        __syncthreads();

        // ---- h1 = relu(x1 @ ff1_w + ff1_b), 2 outputs/thread ----
#pragma unroll
        for (int r = 0; r < 2; r++) {
            int o = tid + r * 1024;
            float acc = 0.0f;
#pragma unroll 4
            for (int d = 0; d < DD; d++) acc += s_x1[d] * ff1_w[d * DII + o];
            acc += ff1_b[o];
            s_h1[o] = fmaxf(acc, 0.0f);
        }
        __syncthreads();

        // ---- inten = LN2(x1 + h1 @ ff2_w + ff2_b), K split across 2 halves ----
        {
            int d = (tid < DD) ? tid : (tid - DD);
            int j0 = (tid < DD) ? 0 : 1024;
            float acc = 0.0f;
#pragma unroll 4
            for (int j = 0; j < 1024; j++) acc += s_h1[j0 + j] * ff2_w[(j0 + j) * DD + d];
            if (tid >= DD) s_part[d] = acc;
            __syncthreads();
            float val = 0.0f;
            if (tid < DD) val = s_x1[tid] + (acc + s_part[tid]) + ff2_b[tid];
            float mean = blockSum(tid < DD ? val : 0.0f, rs) / (float)DD;
            float dv = (tid < DD) ? (val - mean) : 0.0f;
            float var = blockSum(dv * dv, rs) / (float)DD;
            if (tid < DD) s_int[tid] = dv / sqrtf(var + 1e-5f) * ln2_s[tid] + ln2_b[tid];
        }
        __syncthreads();

        // ---- new_time, iml ----
        float tdot = blockSum(tid < DD ? s_int[tid] * tl_w[tid] : 0.0f, rs) + tl_b[0];
        float sp_in = tdot;
        float nt = lt + (fmaxf(sp_in, 0.0f) + log1pf(expf(-fabsf(sp_in))));
        float iml = blockSum(tid < DD ? s_int[tid] * ml_w[EE + tid] : 0.0f, rs);

        // ---- neighbors, nrec, mw ----
        if (tid < SS) {
            s_nb[tid] = g_nlist[lm * SS + tid];
            s_nrec[1 + i * SS + tid] = g_nprob[lm * SS + tid];
        }
        __syncthreads();
        if (tid < SS) {
            float acc = 0.0f;
            const float* ep = &emb[s_nb[tid] * EE];
#pragma unroll 8
            for (int e = 0; e < EE; e++) acc += ep[e] * ml_w[e];
            s_mw[tid] = acc + iml + ml_b[0];
        }
        __syncthreads();
        // softmax over 32 + prob/cand updates (warp 0)
        if (tid < SS) {
            float v = s_mw[tid];
            float mx = v;
#pragma unroll
            for (int o = 16; o > 0; o >>= 1) mx = fmaxf(mx, __shfl_xor_sync(0xffffffffu, mx, o));
            float ex = expf(v - mx);
            float sm = ex;
#pragma unroll
            for (int o = 16; o > 0; o >>= 1) sm += __shfl_xor_sync(0xffffffffu, sm, o);
            float mp = ex / sm;
            float pc = s_prob[chosen];
            __syncwarp();
            float att = pc * mp;
            if (tid == 0) s_prob[chosen] = att;
            else {
                s_prob[1 + i * (SS - 1) + tid - 1] = att;
                s_cand[1 + i * (SS - 1) + tid - 1] = s_nb[tid];
            }
        }
        __syncthreads();

        // ---- categorical over prob_list with key fold_in(key(11), i) ----
        uint32_t ka, kb;
        tf2x32(0u, 11u, 0u, (uint32_t)i, ka, kb);
        float bv = -INFINITY; int bi = 0x7fffffff;
        for (int j = tid; j < LP; j += 1024) {
            float z = logf(s_prob[j]) + gumbel_u32(rbits(ka, kb, (uint32_t)(b * LP + j)));
            if (z > bv) { bv = z; bi = j; }
        }
        blockArgmax(bv, bi, rv, ri);

        if (tid == 0) {
            int nc = bi;
            int nm = s_cand[nc];
            sv_lm = nm; sv_lt = nt; sv_chosen = nc;
            int o = b * TT + (i + 1);
            out[0 * (BB * TT) + o] = (float)nm;
            out[1 * (BB * TT) + o] = nt;
            out[2 * (BB * TT) + o] = (nt < 50.0f) ? 1.0f : 0.0f;
            out[3 * (BB * TT) + o] = s_nrec[nc];
            out[4 * (BB * TT) + o] = s_prob[nc];
        }
        __syncthreads();
    }
}

extern "C" void kernel_launch(void* const* d_in, const int* in_sizes, int n_in,
                              void* d_out, int out_size) {
    const int*   marker = (const int*)  d_in[0];
    const float* timed  = (const float*)d_in[1];
    const float* maskd  = (const float*)d_in[2];
    const float* emb    = (const float*)d_in[3];
    const float* te_w   = (const float*)d_in[4];
    const float* te_b   = (const float*)d_in[5];
    const float* el_w   = (const float*)d_in[6];
    const float* el_b   = (const float*)d_in[7];
    const float* s1_w   = (const float*)d_in[8];
    const float* s1_b   = (const float*)d_in[9];
    const float* s2_w   = (const float*)d_in[10];
    const float* s2_b   = (const float*)d_in[11];
    const float* ml_w   = (const float*)d_in[12];
    const float* ml_b   = (const float*)d_in[13];
    const float* tl_w   = (const float*)d_in[14];
    const float* tl_b   = (const float*)d_in[15];
    const float* wq     = (const float*)d_in[16];
    const float* wk     = (const float*)d_in[17];
    const float* wv     = (const float*)d_in[18];
    const float* wo     = (const float*)d_in[19];
    const float* wo_b   = (const float*)d_in[20];
    const float* ln1_s  = (const float*)d_in[21];
    const float* ln1_b  = (const float*)d_in[22];
    const float* ff1_w  = (const float*)d_in[23];
    const float* ff1_b  = (const float*)d_in[24];
    const float* ff2_w  = (const float*)d_in[25];
    const float* ff2_b  = (const float*)d_in[26];
    const float* ln2_s  = (const float*)d_in[27];
    const float* ln2_b  = (const float*)d_in[28];
    float* out = (float*)d_out;

    k_topk_cand<<<1, 1024>>>();
    k_bm<<<MM, EE>>>(emb, s1_w);
    k_a<<<CC, EE>>>(emb, s1_w);
    k_select<<<MM, CC>>>(s1_b, s2_w, s2_b);
    k_seq<<<BB, 1024>>>(marker, timed, maskd, emb, te_w, te_b, el_w, el_b,
                        ml_w, ml_b, tl_w, tl_b, wq, wk, wv, wo, wo_b,
                        ln1_s, ln1_b, ff1_w, ff1_b, ff2_w, ff2_b, ln2_s, ln2_b,
                        out);
}

// round 4
// speedup vs baseline: 2.3279x; 2.3279x over previous
#include <cuda_runtime.h>
#include <math.h>
#include <stdint.h>

#define MM   5000
#define EE   128
#define DD   512
#define DII  2048
#define HH   8
#define CC   256
#define SS   32
#define BB   32
#define TT   64
#define TMS  63
#define LP   1954
#define LNN  2017

// dynamic smem layout (floats): h1 2048 | scr 4096 | md 512 | q 512 | x1 512 |
// int 512 | ctx 512 | sc 512 | vvec 128 | prob LP | nrec LNN | cand LP (int)
#define SMEM_SEQ_BYTES ((2048 + 4096 + 512*6 + 128 + LP + LNN + LP) * 4)

// ---------------- device scratch ----------------
__device__ int   g_cand[CC];
__device__ float g_At[EE * CC];
__device__ float g_Bm[MM * EE];
__device__ int   g_nlist[MM * SS];
__device__ float g_nprob[MM * SS];
__device__ float g_kc[BB * TMS * DD];
__device__ float g_vc[BB * TMS * DD];

// ---------------- threefry2x32 (JAX partitionable semantics) ----------------
__device__ __forceinline__ void tf2x32(uint32_t k0, uint32_t k1,
                                       uint32_t x0, uint32_t x1,
                                       uint32_t& o0, uint32_t& o1) {
    uint32_t k2 = k0 ^ k1 ^ 0x1BD11BDAu;
    x0 += k0; x1 += k1;
#define TF_R(r) { x0 += x1; x1 = (x1 << r) | (x1 >> (32 - r)); x1 ^= x0; }
    TF_R(13) TF_R(15) TF_R(26) TF_R(6)   x0 += k1; x1 += k2 + 1u;
    TF_R(17) TF_R(29) TF_R(16) TF_R(24)  x0 += k2; x1 += k0 + 2u;
    TF_R(13) TF_R(15) TF_R(26) TF_R(6)   x0 += k0; x1 += k1 + 3u;
    TF_R(17) TF_R(29) TF_R(16) TF_R(24)  x0 += k1; x1 += k2 + 4u;
    TF_R(13) TF_R(15) TF_R(26) TF_R(6)   x0 += k2; x1 += k0 + 5u;
#undef TF_R
    o0 = x0; o1 = x1;
}

__device__ __forceinline__ uint32_t rbits(uint32_t k0, uint32_t k1, uint32_t idx) {
    uint32_t a, b;
    tf2x32(k0, k1, 0u, idx, a, b);
    return a ^ b;
}

__device__ __forceinline__ float gumbel_u32(uint32_t bits) {
    const float tiny = 1.17549435e-38f;
    float f = __uint_as_float((bits >> 9) | 0x3f800000u) - 1.0f;
    float u = fmaxf(tiny, f + tiny);
    return -logf(-logf(u));
}

// ---------------- block reductions ----------------
__device__ __forceinline__ float blockSum(float v, float* rs) {
    int tid = threadIdx.x, w = tid >> 5, l = tid & 31, nw = blockDim.x >> 5;
#pragma unroll
    for (int o = 16; o > 0; o >>= 1) v += __shfl_xor_sync(0xffffffffu, v, o);
    if (l == 0) rs[w] = v;
    __syncthreads();
    if (w == 0) {
        float x = (l < nw) ? rs[l] : 0.0f;
#pragma unroll
        for (int o = 16; o > 0; o >>= 1) x += __shfl_xor_sync(0xffffffffu, x, o);
        if (l == 0) rs[0] = x;
    }
    __syncthreads();
    float r = rs[0];
    __syncthreads();
    return r;
}

__device__ __forceinline__ float blockMax(float v, float* rs) {
    int tid = threadIdx.x, w = tid >> 5, l = tid & 31, nw = blockDim.x >> 5;
#pragma unroll
    for (int o = 16; o > 0; o >>= 1) v = fmaxf(v, __shfl_xor_sync(0xffffffffu, v, o));
    if (l == 0) rs[w] = v;
    __syncthreads();
    if (w == 0) {
        float x = (l < nw) ? rs[l] : -INFINITY;
#pragma unroll
        for (int o = 16; o > 0; o >>= 1) x = fmaxf(x, __shfl_xor_sync(0xffffffffu, x, o));
        if (l == 0) rs[0] = x;
    }
    __syncthreads();
    float r = rs[0];
    __syncthreads();
    return r;
}

__device__ __forceinline__ void warpArgmax(float& v, int& idx) {
#pragma unroll
    for (int o = 16; o > 0; o >>= 1) {
        float ov = __shfl_xor_sync(0xffffffffu, v, o);
        int   oi = __shfl_xor_sync(0xffffffffu, idx, o);
        if (ov > v || (ov == v && oi < idx)) { v = ov; idx = oi; }
    }
}

__device__ __forceinline__ void blockArgmax(float& v, int& idx, float* rv, int* ri) {
    int tid = threadIdx.x, w = tid >> 5, l = tid & 31, nw = (blockDim.x + 31) >> 5;
    warpArgmax(v, idx);
    if (l == 0) { rv[w] = v; ri[w] = idx; }
    __syncthreads();
    if (w == 0) {
        float vv = (l < nw) ? rv[l] : -INFINITY;
        int   ii = (l < nw) ? ri[l] : 0x7fffffff;
        warpArgmax(vv, ii);
        if (l == 0) { rv[0] = vv; ri[0] = ii; }
    }
    __syncthreads();
    v = rv[0]; idx = ri[0];
    __syncthreads();
}

// ---------------- kernel 1: gumbel(k1,(M,)) top-256 -> g_cand ----------------
__global__ void __launch_bounds__(1024) k_topk_cand() {
    __shared__ float vals[MM];
    __shared__ float rv[32];
    __shared__ int   ri[32];
    uint32_t ka, kb;
    tf2x32(0u, 7u, 0u, 0u, ka, kb);
    for (int i = threadIdx.x; i < MM; i += blockDim.x)
        vals[i] = gumbel_u32(rbits(ka, kb, (uint32_t)i));
    __syncthreads();
    for (int r = 0; r < CC; r++) {
        float bv = -INFINITY; int bi = 0x7fffffff;
        for (int i = threadIdx.x; i < MM; i += blockDim.x) {
            float v = vals[i];
            if (v > bv) { bv = v; bi = i; }
        }
        blockArgmax(bv, bi, rv, ri);
        if (threadIdx.x == 0) { g_cand[r] = bi; vals[bi] = -INFINITY; }
        __syncthreads();
    }
}

// ---------------- kernel 2: Bm = emb @ s1_w[E:] ----------------
__global__ void __launch_bounds__(EE) k_bm(const float* __restrict__ emb,
                                           const float* __restrict__ s1w) {
    __shared__ float se[EE];
    int m = blockIdx.x, d = threadIdx.x;
    se[d] = emb[m * EE + d];
    __syncthreads();
    float acc = 0.0f;
#pragma unroll 8
    for (int e = 0; e < EE; e++) acc += se[e] * s1w[(EE + e) * EE + d];
    g_Bm[m * EE + d] = acc;
}

// ---------------- kernel 3: At = (emb[cand] @ s1_w[:E])^T ----------------
__global__ void __launch_bounds__(EE) k_a(const float* __restrict__ emb,
                                          const float* __restrict__ s1w) {
    __shared__ float se[EE];
    int c = blockIdx.x, d = threadIdx.x;
    int mm = g_cand[c];
    se[d] = emb[mm * EE + d];
    __syncthreads();
    float acc = 0.0f;
#pragma unroll 8
    for (int e = 0; e < EE; e++) acc += se[e] * s1w[e * EE + d];
    g_At[d * CC + c] = acc;
}

// ---------------- kernel 4: softmax over 256 cand + gumbel top-32 ----------------
__global__ void __launch_bounds__(CC) k_select(const float* __restrict__ s1b,
                                               const float* __restrict__ s2w,
                                               const float* __restrict__ s2b) {
    __shared__ float sb[EE], sw[EE], sbm[EE];
    __shared__ float p[CC], sc[CC];
    __shared__ float rs[32];
    __shared__ float rv[32];
    __shared__ int   ri[32];
    int m = blockIdx.x, c = threadIdx.x;
    if (c < EE) { sb[c] = s1b[c]; sw[c] = s2w[c]; sbm[c] = g_Bm[m * EE + c]; }
    __syncthreads();
    float acc = 0.0f;
#pragma unroll 4
    for (int e = 0; e < EE; e++) {
        float t = g_At[e * CC + c] + sbm[e] + sb[e];
        t = (t >= 0.0f) ? t : 0.01f * t;
        acc += t * sw[e];
    }
    float logit = acc + s2b[0];
    float mx = blockMax(logit, rs);
    float ex = expf(logit - mx);
    float sm = blockSum(ex, rs);
    float pc = ex / sm;
    p[c] = pc;
    uint32_t ka, kb;
    tf2x32(0u, 7u, 0u, 1u, ka, kb);
    sc[c] = logf(pc) + gumbel_u32(rbits(ka, kb, (uint32_t)(m * CC + c)));
    __syncthreads();
    for (int s = 0; s < SS; s++) {
        float bv = sc[c]; int bi = c;
        blockArgmax(bv, bi, rv, ri);
        if (threadIdx.x == 0) {
            g_nlist[m * SS + s] = g_cand[bi];
            g_nprob[m * SS + s] = p[bi];
            sc[bi] = -INFINITY;
        }
        __syncthreads();
    }
}

// GEMV panel: every thread computes 4 output cols (float4 weight loads),
// K split across P partitions; partials land in s_scr[p*N + n].
// N*P/4 must equal 1024. KC = K/P.
#define GEMV_PANEL(W, XVEC, N, P, KC)                                        \
    {                                                                        \
        const int g = tid & ((N/4) - 1);                                     \
        const int p = tid / (N/4);                                           \
        const int kb0 = p * (KC);                                            \
        float4 acc = make_float4(0.f, 0.f, 0.f, 0.f);                        \
        _Pragma("unroll 8")                                                  \
        for (int kk = 0; kk < (KC); kk++) {                                  \
            float x = (XVEC)[kb0 + kk];                                      \
            float4 w4 = ((const float4*)(W))[(kb0 + kk) * ((N)/4) + g];      \
            acc.x += x * w4.x; acc.y += x * w4.y;                            \
            acc.z += x * w4.z; acc.w += x * w4.w;                            \
        }                                                                    \
        ((float4*)s_scr)[p * ((N)/4) + g] = acc;                             \
    }                                                                        \
    __syncthreads();

// ---------------- kernel 5: 63-step scan, one block per batch row ----------------
__global__ void __launch_bounds__(1024) k_seq(
    const int*   __restrict__ marker_data, const float* __restrict__ time_data,
    const float* __restrict__ mask_data,   const float* __restrict__ emb,
    const float* __restrict__ te_w, const float* __restrict__ te_b,
    const float* __restrict__ el_w, const float* __restrict__ el_b,
    const float* __restrict__ ml_w, const float* __restrict__ ml_b,
    const float* __restrict__ tl_w, const float* __restrict__ tl_b,
    const float* __restrict__ wq,   const float* __restrict__ wk,
    const float* __restrict__ wv,   const float* __restrict__ wo,
    const float* __restrict__ wo_b,
    const float* __restrict__ ln1_s, const float* __restrict__ ln1_b,
    const float* __restrict__ ff1_w, const float* __restrict__ ff1_b,
    const float* __restrict__ ff2_w, const float* __restrict__ ff2_b,
    const float* __restrict__ ln2_s, const float* __restrict__ ln2_b,
    float* __restrict__ out)
{
    const int b = blockIdx.x, tid = threadIdx.x;

    extern __shared__ float smb[];
    float* s_h1   = smb;                 // 2048
    float* s_scr  = s_h1 + 2048;         // 4096
    float* s_md   = s_scr + 4096;        // 512
    float* s_q    = s_md + 512;          // 512
    float* s_x1   = s_q + 512;           // 512
    float* s_int  = s_x1 + 512;          // 512
    float* s_ctx  = s_int + 512;         // 512
    float* s_sc   = s_ctx + 512;         // 512
    float* s_vvec = s_sc + 512;          // 128
    float* s_prob = s_vvec + 128;        // LP
    float* s_nrec = s_prob + LP;         // LNN
    int*   s_cand = (int*)(s_nrec + LNN);// LP

    __shared__ float rs[32];
    __shared__ float rv[32];
    __shared__ int   ri[32];
    __shared__ float s_mw[SS];
    __shared__ int   s_nb[SS];
    __shared__ float sv_lt;
    __shared__ int   sv_lm, sv_chosen;

    for (int j = tid; j < LP;  j += 1024) { s_prob[j] = 0.0f; s_cand[j] = 0; }
    for (int j = tid; j < LNN; j += 1024) s_nrec[j] = 0.0f;
    if (tid == 0) {
        int   m0 = marker_data[b * TT];
        float t0 = time_data[b * TT];
        s_prob[0] = 1.0f; s_cand[0] = m0; s_nrec[0] = 1.0f;
        sv_lm = m0; sv_lt = t0; sv_chosen = 0;
        out[0 * (BB * TT) + b * TT] = (float)m0;
        out[1 * (BB * TT) + b * TT] = t0;
        out[2 * (BB * TT) + b * TT] = mask_data[b * TT];
        out[3 * (BB * TT) + b * TT] = 1.0f;
        out[4 * (BB * TT) + b * TT] = 1.0f;
    }
    __syncthreads();

    for (int i = 0; i < TMS; i++) {
        const int   lm = sv_lm;
        const float lt = sv_lt;
        const int   chosen = sv_chosen;

        // ---- vvec ----
        if (tid < EE) s_vvec[tid] = emb[lm * EE + tid] + 0.1f * (lt * te_w[tid] + te_b[tid]);
        __syncthreads();

        // ---- md = lrelu(vvec @ el_w + el_b): N=512,K=128,P=8,KC=16 ----
        GEMV_PANEL(el_w, s_vvec, 512, 8, 16)
        if (tid < DD) {
            float s = el_b[tid];
#pragma unroll
            for (int p = 0; p < 8; p++) s += s_scr[p * 512 + tid];
            s_md[tid] = (s >= 0.0f) ? s : 0.01f * s;
        }
        __syncthreads();

        // ---- q = md @ wq ----
        GEMV_PANEL(wq, s_md, 512, 8, 64)
        if (tid < DD) {
            float s = 0.0f;
#pragma unroll
            for (int p = 0; p < 8; p++) s += s_scr[p * 512 + tid];
            s_q[tid] = s;
        }
        __syncthreads();
        // ---- k = md @ wk -> g_kc[b][i] ----
        GEMV_PANEL(wk, s_md, 512, 8, 64)
        if (tid < DD) {
            float s = 0.0f;
#pragma unroll
            for (int p = 0; p < 8; p++) s += s_scr[p * 512 + tid];
            g_kc[(b * TMS + i) * DD + tid] = s;
        }
        __syncthreads();
        // ---- v = md @ wv -> g_vc[b][i] ----
        GEMV_PANEL(wv, s_md, 512, 8, 64)
        if (tid < DD) {
            float s = 0.0f;
#pragma unroll
            for (int p = 0; p < 8; p++) s += s_scr[p * 512 + tid];
            g_vc[(b * TMS + i) * DD + tid] = s;
        }
        __syncthreads();

        // ---- attention scores sc[h][t] (t<=i), float4 dots ----
        if (tid < HH * (i + 1)) {
            int t = tid >> 3, h = tid & 7;
            const float4* kp = (const float4*)&g_kc[(b * TMS + t) * DD + h * 64];
            const float4* qp = (const float4*)&s_q[h * 64];
            float acc = 0.0f;
#pragma unroll
            for (int d = 0; d < 16; d++) {
                float4 a = qp[d], k4 = kp[d];
                acc += a.x * k4.x + a.y * k4.y + a.z * k4.z + a.w * k4.w;
            }
            s_sc[h * 64 + t] = acc * 0.125f;
        }
        __syncthreads();

        // ---- per-head softmax over t<=i ----
        if (tid < HH) {
            int h = tid;
            float mx = -INFINITY;
            for (int t = 0; t <= i; t++) mx = fmaxf(mx, s_sc[h * 64 + t]);
            float sm = 0.0f;
            for (int t = 0; t <= i; t++) { float e = expf(s_sc[h * 64 + t] - mx); s_sc[h * 64 + t] = e; sm += e; }
            for (int t = 0; t <= i; t++) s_sc[h * 64 + t] /= sm;
        }
        __syncthreads();

        // ---- ctx ----
        if (tid < DD) {
            int h = tid >> 6;
            float acc = 0.0f;
            for (int t = 0; t <= i; t++) acc += s_sc[h * 64 + t] * g_vc[(b * TMS + t) * DD + tid];
            s_ctx[tid] = acc;
        }
        __syncthreads();

        // ---- x1 = LN1(md + ctx@wo + wo_b) ----
        GEMV_PANEL(wo, s_ctx, 512, 8, 64)
        {
            float val = 0.0f;
            if (tid < DD) {
                float s = wo_b[tid];
#pragma unroll
                for (int p = 0; p < 8; p++) s += s_scr[p * 512 + tid];
                val = s_md[tid] + s;
            }
            float mean = blockSum(tid < DD ? val : 0.0f, rs) / (float)DD;
            float dv = (tid < DD) ? (val - mean) : 0.0f;
            float var = blockSum(dv * dv, rs) / (float)DD;
            if (tid < DD) s_x1[tid] = dv / sqrtf(var + 1e-5f) * ln1_s[tid] + ln1_b[tid];
        }
        __syncthreads();

        // ---- h1 = relu(x1 @ ff1_w + ff1_b): N=2048,K=512,P=2,KC=256 ----
        GEMV_PANEL(ff1_w, s_x1, 2048, 2, 256)
#pragma unroll
        for (int r = 0; r < 2; r++) {
            int n = tid + r * 1024;
            float v = s_scr[n] + s_scr[2048 + n] + ff1_b[n];
            s_h1[n] = fmaxf(v, 0.0f);
        }
        __syncthreads();

        // ---- inten = LN2(x1 + h1 @ ff2_w + ff2_b): N=512,K=2048,P=8,KC=256 ----
        GEMV_PANEL(ff2_w, s_h1, 512, 8, 256)
        {
            float val = 0.0f;
            if (tid < DD) {
                float s = ff2_b[tid];
#pragma unroll
                for (int p = 0; p < 8; p++) s += s_scr[p * 512 + tid];
                val = s_x1[tid] + s;
            }
            float mean = blockSum(tid < DD ? val : 0.0f, rs) / (float)DD;
            float dv = (tid < DD) ? (val - mean) : 0.0f;
            float var = blockSum(dv * dv, rs) / (float)DD;
            if (tid < DD) s_int[tid] = dv / sqrtf(var + 1e-5f) * ln2_s[tid] + ln2_b[tid];
        }
        __syncthreads();

        // ---- new_time, iml ----
        float tdot = blockSum(tid < DD ? s_int[tid] * tl_w[tid] : 0.0f, rs) + tl_b[0];
        float nt = lt + (fmaxf(tdot, 0.0f) + log1pf(expf(-fabsf(tdot))));
        float iml = blockSum(tid < DD ? s_int[tid] * ml_w[EE + tid] : 0.0f, rs);

        // ---- neighbors, nrec, mw ----
        if (tid < SS) {
            s_nb[tid] = g_nlist[lm * SS + tid];
            s_nrec[1 + i * SS + tid] = g_nprob[lm * SS + tid];
        }
        __syncthreads();
        if (tid < SS) {
            float acc = 0.0f;
            const float* ep = &emb[s_nb[tid] * EE];
#pragma unroll 8
            for (int e = 0; e < EE; e++) acc += ep[e] * ml_w[e];
            s_mw[tid] = acc + iml + ml_b[0];
        }
        __syncthreads();
        if (tid < SS) {
            float v = s_mw[tid];
            float mx = v;
#pragma unroll
            for (int o = 16; o > 0; o >>= 1) mx = fmaxf(mx, __shfl_xor_sync(0xffffffffu, mx, o));
            float ex = expf(v - mx);
            float sm = ex;
#pragma unroll
            for (int o = 16; o > 0; o >>= 1) sm += __shfl_xor_sync(0xffffffffu, sm, o);
            float mp = ex / sm;
            float pc = s_prob[chosen];
            __syncwarp();
            float att = pc * mp;
            if (tid == 0) s_prob[chosen] = att;
            else {
                s_prob[1 + i * (SS - 1) + tid - 1] = att;
                s_cand[1 + i * (SS - 1) + tid - 1] = s_nb[tid];
            }
        }
        __syncthreads();

        // ---- categorical with key fold_in(key(11), i) ----
        uint32_t ka, kb;
        tf2x32(0u, 11u, 0u, (uint32_t)i, ka, kb);
        float bv = -INFINITY; int bi = 0x7fffffff;
        for (int j = tid; j < LP; j += 1024) {
            float z = logf(s_prob[j]) + gumbel_u32(rbits(ka, kb, (uint32_t)(b * LP + j)));
            if (z > bv) { bv = z; bi = j; }
        }
        blockArgmax(bv, bi, rv, ri);

        if (tid == 0) {
            int nc = bi;
            int nm = s_cand[nc];
            sv_lm = nm; sv_lt = nt; sv_chosen = nc;
            int o = b * TT + (i + 1);
            out[0 * (BB * TT) + o] = (float)nm;
            out[1 * (BB * TT) + o] = nt;
            out[2 * (BB * TT) + o] = (nt < 50.0f) ? 1.0f : 0.0f;
            out[3 * (BB * TT) + o] = s_nrec[nc];
            out[4 * (BB * TT) + o] = s_prob[nc];
        }
        __syncthreads();
    }
}

extern "C" void kernel_launch(void* const* d_in, const int* in_sizes, int n_in,
                              void* d_out, int out_size) {
    const int*   marker = (const int*)  d_in[0];
    const float* timed  = (const float*)d_in[1];
    const float* maskd  = (const float*)d_in[2];
    const float* emb    = (const float*)d_in[3];
    const float* te_w   = (const float*)d_in[4];
    const float* te_b   = (const float*)d_in[5];
    const float* el_w   = (const float*)d_in[6];
    const float* el_b   = (const float*)d_in[7];
    const float* s1_w   = (const float*)d_in[8];
    const float* s1_b   = (const float*)d_in[9];
    const float* s2_w   = (const float*)d_in[10];
    const float* s2_b   = (const float*)d_in[11];
    const float* ml_w   = (const float*)d_in[12];
    const float* ml_b   = (const float*)d_in[13];
    const float* tl_w   = (const float*)d_in[14];
    const float* tl_b   = (const float*)d_in[15];
    const float* wq     = (const float*)d_in[16];
    const float* wk     = (const float*)d_in[17];
    const float* wv     = (const float*)d_in[18];
    const float* wo     = (const float*)d_in[19];
    const float* wo_b   = (const float*)d_in[20];
    const float* ln1_s  = (const float*)d_in[21];
    const float* ln1_b  = (const float*)d_in[22];
    const float* ff1_w  = (const float*)d_in[23];
    const float* ff1_b  = (const float*)d_in[24];
    const float* ff2_w  = (const float*)d_in[25];
    const float* ff2_b  = (const float*)d_in[26];
    const float* ln2_s  = (const float*)d_in[27];
    const float* ln2_b  = (const float*)d_in[28];
    float* out = (float*)d_out;

    static int smem_set = 0;
    if (!smem_set) {
        cudaFuncSetAttribute(k_seq, cudaFuncAttributeMaxDynamicSharedMemorySize,
                             SMEM_SEQ_BYTES);
        smem_set = 1;
    }

    k_topk_cand<<<1, 1024>>>();
    k_bm<<<MM, EE>>>(emb, s1_w);
    k_a<<<CC, EE>>>(emb, s1_w);
    k_select<<<MM, CC>>>(s1_b, s2_w, s2_b);
    k_seq<<<BB, 1024, SMEM_SEQ_BYTES>>>(marker, timed, maskd, emb, te_w, te_b,
                        el_w, el_b, ml_w, ml_b, tl_w, tl_b, wq, wk, wv, wo, wo_b,
                        ln1_s, ln1_b, ff1_w, ff1_b, ff2_w, ff2_b, ln2_s, ln2_b,
                        out);
}

// round 5
// speedup vs baseline: 2.3475x; 1.0084x over previous
#include <cuda_runtime.h>
#include <math.h>
#include <stdint.h>

#define MM   5000
#define EE   128
#define DD   512
#define DII  2048
#define HH   8
#define CC   256
#define SS   32
#define BB   32
#define TT   64
#define TMS  63
#define LP   1954
#define LNN  2017

// dynamic smem layout (floats): h1 2048 | scr 4096 | md 512 | q 512 | x1 512 |
// int 512 | ctx 512 | sc 512 | vvec 128 | prob LP | nrec LNN | cand LP (int)
#define SMEM_SEQ_BYTES ((2048 + 4096 + 512*6 + 128 + LP + LNN + LP) * 4)

// ---------------- device scratch ----------------
__device__ int   g_cand[CC];
__device__ float g_At[EE * CC];
__device__ float g_Bm[MM * EE];
__device__ int   g_nlist[MM * SS];
__device__ float g_nprob[MM * SS];
__device__ float g_kc[BB * TMS * DD];
__device__ float g_vc[BB * TMS * DD];

// ---------------- threefry2x32 (JAX partitionable semantics) ----------------
__device__ __forceinline__ void tf2x32(uint32_t k0, uint32_t k1,
                                       uint32_t x0, uint32_t x1,
                                       uint32_t& o0, uint32_t& o1) {
    uint32_t k2 = k0 ^ k1 ^ 0x1BD11BDAu;
    x0 += k0; x1 += k1;
#define TF_R(r) { x0 += x1; x1 = (x1 << r) | (x1 >> (32 - r)); x1 ^= x0; }
    TF_R(13) TF_R(15) TF_R(26) TF_R(6)   x0 += k1; x1 += k2 + 1u;
    TF_R(17) TF_R(29) TF_R(16) TF_R(24)  x0 += k2; x1 += k0 + 2u;
    TF_R(13) TF_R(15) TF_R(26) TF_R(6)   x0 += k0; x1 += k1 + 3u;
    TF_R(17) TF_R(29) TF_R(16) TF_R(24)  x0 += k1; x1 += k2 + 4u;
    TF_R(13) TF_R(15) TF_R(26) TF_R(6)   x0 += k2; x1 += k0 + 5u;
#undef TF_R
    o0 = x0; o1 = x1;
}

__device__ __forceinline__ uint32_t rbits(uint32_t k0, uint32_t k1, uint32_t idx) {
    uint32_t a, b;
    tf2x32(k0, k1, 0u, idx, a, b);
    return a ^ b;
}

__device__ __forceinline__ float gumbel_u32(uint32_t bits) {
    const float tiny = 1.17549435e-38f;
    float f = __uint_as_float((bits >> 9) | 0x3f800000u) - 1.0f;
    float u = fmaxf(tiny, f + tiny);
    return -logf(-logf(u));
}

// ---------------- block reductions ----------------
__device__ __forceinline__ float blockSum(float v, float* rs) {
    int tid = threadIdx.x, w = tid >> 5, l = tid & 31, nw = blockDim.x >> 5;
#pragma unroll
    for (int o = 16; o > 0; o >>= 1) v += __shfl_xor_sync(0xffffffffu, v, o);
    if (l == 0) rs[w] = v;
    __syncthreads();
    if (w == 0) {
        float x = (l < nw) ? rs[l] : 0.0f;
#pragma unroll
        for (int o = 16; o > 0; o >>= 1) x += __shfl_xor_sync(0xffffffffu, x, o);
        if (l == 0) rs[0] = x;
    }
    __syncthreads();
    float r = rs[0];
    __syncthreads();
    return r;
}

__device__ __forceinline__ float blockMax(float v, float* rs) {
    int tid = threadIdx.x, w = tid >> 5, l = tid & 31, nw = blockDim.x >> 5;
#pragma unroll
    for (int o = 16; o > 0; o >>= 1) v = fmaxf(v, __shfl_xor_sync(0xffffffffu, v, o));
    if (l == 0) rs[w] = v;
    __syncthreads();
    if (w == 0) {
        float x = (l < nw) ? rs[l] : -INFINITY;
#pragma unroll
        for (int o = 16; o > 0; o >>= 1) x = fmaxf(x, __shfl_xor_sync(0xffffffffu, x, o));
        if (l == 0) rs[0] = x;
    }
    __syncthreads();
    float r = rs[0];
    __syncthreads();
    return r;
}

__device__ __forceinline__ void warpArgmax(float& v, int& idx) {
#pragma unroll
    for (int o = 16; o > 0; o >>= 1) {
        float ov = __shfl_xor_sync(0xffffffffu, v, o);
        int   oi = __shfl_xor_sync(0xffffffffu, idx, o);
        if (ov > v || (ov == v && oi < idx)) { v = ov; idx = oi; }
    }
}

__device__ __forceinline__ void blockArgmax(float& v, int& idx, float* rv, int* ri) {
    int tid = threadIdx.x, w = tid >> 5, l = tid & 31, nw = (blockDim.x + 31) >> 5;
    warpArgmax(v, idx);
    if (l == 0) { rv[w] = v; ri[w] = idx; }
    __syncthreads();
    if (w == 0) {
        float vv = (l < nw) ? rv[l] : -INFINITY;
        int   ii = (l < nw) ? ri[l] : 0x7fffffff;
        warpArgmax(vv, ii);
        if (l == 0) { rv[0] = vv; ri[0] = ii; }
    }
    __syncthreads();
    v = rv[0]; idx = ri[0];
    __syncthreads();
}

// ---------------- kernel 1: gumbel(k1,(M,)) top-256 -> g_cand ----------------
__global__ void __launch_bounds__(1024) k_topk_cand() {
    __shared__ float vals[MM];
    __shared__ float rv[32];
    __shared__ int   ri[32];
    uint32_t ka, kb;
    tf2x32(0u, 7u, 0u, 0u, ka, kb);
    for (int i = threadIdx.x; i < MM; i += blockDim.x)
        vals[i] = gumbel_u32(rbits(ka, kb, (uint32_t)i));
    __syncthreads();
    for (int r = 0; r < CC; r++) {
        float bv = -INFINITY; int bi = 0x7fffffff;
        for (int i = threadIdx.x; i < MM; i += blockDim.x) {
            float v = vals[i];
            if (v > bv) { bv = v; bi = i; }
        }
        blockArgmax(bv, bi, rv, ri);
        if (threadIdx.x == 0) { g_cand[r] = bi; vals[bi] = -INFINITY; }
        __syncthreads();
    }
}

// ---------------- kernel 2: Bm = emb @ s1_w[E:] ----------------
__global__ void __launch_bounds__(EE) k_bm(const float* __restrict__ emb,
                                           const float* __restrict__ s1w) {
    __shared__ float se[EE];
    int m = blockIdx.x, d = threadIdx.x;
    se[d] = emb[m * EE + d];
    __syncthreads();
    float acc = 0.0f;
#pragma unroll 8
    for (int e = 0; e < EE; e++) acc += se[e] * s1w[(EE + e) * EE + d];
    g_Bm[m * EE + d] = acc;
}

// ---------------- kernel 3: At = (emb[cand] @ s1_w[:E])^T ----------------
__global__ void __launch_bounds__(EE) k_a(const float* __restrict__ emb,
                                          const float* __restrict__ s1w) {
    __shared__ float se[EE];
    int c = blockIdx.x, d = threadIdx.x;
    int mm = g_cand[c];
    se[d] = emb[mm * EE + d];
    __syncthreads();
    float acc = 0.0f;
#pragma unroll 8
    for (int e = 0; e < EE; e++) acc += se[e] * s1w[e * EE + d];
    g_At[d * CC + c] = acc;
}

// ---------------- kernel 4: softmax over 256 cand + gumbel top-32 ----------------
__global__ void __launch_bounds__(CC) k_select(const float* __restrict__ s1b,
                                               const float* __restrict__ s2w,
                                               const float* __restrict__ s2b) {
    __shared__ float sb[EE], sw[EE], sbm[EE];
    __shared__ float p[CC], sc[CC];
    __shared__ float rs[32];
    __shared__ float rv[32];
    __shared__ int   ri[32];
    int m = blockIdx.x, c = threadIdx.x;
    if (c < EE) { sb[c] = s1b[c]; sw[c] = s2w[c]; sbm[c] = g_Bm[m * EE + c]; }
    __syncthreads();
    float acc = 0.0f;
#pragma unroll 4
    for (int e = 0; e < EE; e++) {
        float t = g_At[e * CC + c] + sbm[e] + sb[e];
        t = (t >= 0.0f) ? t : 0.01f * t;
        acc += t * sw[e];
    }
    float logit = acc + s2b[0];
    float mx = blockMax(logit, rs);
    float ex = expf(logit - mx);
    float sm = blockSum(ex, rs);
    float pc = ex / sm;
    p[c] = pc;
    uint32_t ka, kb;
    tf2x32(0u, 7u, 0u, 1u, ka, kb);
    sc[c] = logf(pc) + gumbel_u32(rbits(ka, kb, (uint32_t)(m * CC + c)));
    __syncthreads();
    for (int s = 0; s < SS; s++) {
        float bv = sc[c]; int bi = c;
        blockArgmax(bv, bi, rv, ri);
        if (threadIdx.x == 0) {
            g_nlist[m * SS + s] = g_cand[bi];
            g_nprob[m * SS + s] = p[bi];
            sc[bi] = -INFINITY;
        }
        __syncthreads();
    }
}

// GEMV panel: every thread computes 4 output cols (float4 weight loads),
// K split across P partitions; partials land in s_scr[p*N + n].
// N*P/4 must equal 1024. KC = K/P.
#define GEMV_PANEL(W, XVEC, N, P, KC)                                        \
    {                                                                        \
        const int g = tid & ((N/4) - 1);                                     \
        const int p = tid / (N/4);                                           \
        const int kb0 = p * (KC);                                            \
        float4 acc = make_float4(0.f, 0.f, 0.f, 0.f);                        \
        _Pragma("unroll 8")                                                  \
        for (int kk = 0; kk < (KC); kk++) {                                  \
            float x = (XVEC)[kb0 + kk];                                      \
            float4 w4 = ((const float4*)(W))[(kb0 + kk) * ((N)/4) + g];      \
            acc.x += x * w4.x; acc.y += x * w4.y;                            \
            acc.z += x * w4.z; acc.w += x * w4.w;                            \
        }                                                                    \
        ((float4*)s_scr)[p * ((N)/4) + g] = acc;                             \
    }                                                                        \
    __syncthreads();

// ---------------- kernel 5: 63-step scan, one block per batch row ----------------
__global__ void __launch_bounds__(1024) k_seq(
    const int*   __restrict__ marker_data, const float* __restrict__ time_data,
    const float* __restrict__ mask_data,   const float* __restrict__ emb,
    const float* __restrict__ te_w, const float* __restrict__ te_b,
    const float* __restrict__ el_w, const float* __restrict__ el_b,
    const float* __restrict__ ml_w, const float* __restrict__ ml_b,
    const float* __restrict__ tl_w, const float* __restrict__ tl_b,
    const float* __restrict__ wq,   const float* __restrict__ wk,
    const float* __restrict__ wv,   const float* __restrict__ wo,
    const float* __restrict__ wo_b,
    const float* __restrict__ ln1_s, const float* __restrict__ ln1_b,
    const float* __restrict__ ff1_w, const float* __restrict__ ff1_b,
    const float* __restrict__ ff2_w, const float* __restrict__ ff2_b,
    const float* __restrict__ ln2_s, const float* __restrict__ ln2_b,
    float* __restrict__ out)
{
    const int b = blockIdx.x, tid = threadIdx.x;

    extern __shared__ float smb[];
    float* s_h1   = smb;                 // 2048
    float* s_scr  = s_h1 + 2048;         // 4096
    float* s_md   = s_scr + 4096;        // 512
    float* s_q    = s_md + 512;          // 512
    float* s_x1   = s_q + 512;           // 512
    float* s_int  = s_x1 + 512;          // 512
    float* s_ctx  = s_int + 512;         // 512
    float* s_sc   = s_ctx + 512;         // 512
    float* s_vvec = s_sc + 512;          // 128
    float* s_prob = s_vvec + 128;        // LP
    float* s_nrec = s_prob + LP;         // LNN
    int*   s_cand = (int*)(s_nrec + LNN);// LP

    __shared__ float rs[32];
    __shared__ float rv[32];
    __shared__ int   ri[32];
    __shared__ float s_mw[SS];
    __shared__ int   s_nb[SS];
    __shared__ float sv_lt;
    __shared__ int   sv_lm, sv_chosen;

    for (int j = tid; j < LP;  j += 1024) { s_prob[j] = 0.0f; s_cand[j] = 0; }
    for (int j = tid; j < LNN; j += 1024) s_nrec[j] = 0.0f;
    if (tid == 0) {
        int   m0 = marker_data[b * TT];
        float t0 = time_data[b * TT];
        s_prob[0] = 1.0f; s_cand[0] = m0; s_nrec[0] = 1.0f;
        sv_lm = m0; sv_lt = t0; sv_chosen = 0;
        out[0 * (BB * TT) + b * TT] = (float)m0;
        out[1 * (BB * TT) + b * TT] = t0;
        out[2 * (BB * TT) + b * TT] = mask_data[b * TT];
        out[3 * (BB * TT) + b * TT] = 1.0f;
        out[4 * (BB * TT) + b * TT] = 1.0f;
    }
    __syncthreads();

    for (int i = 0; i < TMS; i++) {
        const int   lm = sv_lm;
        const float lt = sv_lt;
        const int   chosen = sv_chosen;

        // ---- vvec ----
        if (tid < EE) s_vvec[tid] = emb[lm * EE + tid] + 0.1f * (lt * te_w[tid] + te_b[tid]);
        __syncthreads();

        // ---- md = lrelu(vvec @ el_w + el_b): N=512,K=128,P=8,KC=16 ----
        GEMV_PANEL(el_w, s_vvec, 512, 8, 16)
        if (tid < DD) {
            float s = el_b[tid];
#pragma unroll
            for (int p = 0; p < 8; p++) s += s_scr[p * 512 + tid];
            s_md[tid] = (s >= 0.0f) ? s : 0.01f * s;
        }
        __syncthreads();

        // ---- q = md @ wq ----
        GEMV_PANEL(wq, s_md, 512, 8, 64)
        if (tid < DD) {
            float s = 0.0f;
#pragma unroll
            for (int p = 0; p < 8; p++) s += s_scr[p * 512 + tid];
            s_q[tid] = s;
        }
        __syncthreads();
        // ---- k = md @ wk -> g_kc[b][i] ----
        GEMV_PANEL(wk, s_md, 512, 8, 64)
        if (tid < DD) {
            float s = 0.0f;
#pragma unroll
            for (int p = 0; p < 8; p++) s += s_scr[p * 512 + tid];
            g_kc[(b * TMS + i) * DD + tid] = s;
        }
        __syncthreads();
        // ---- v = md @ wv -> g_vc[b][i] ----
        GEMV_PANEL(wv, s_md, 512, 8, 64)
        if (tid < DD) {
            float s = 0.0f;
#pragma unroll
            for (int p = 0; p < 8; p++) s += s_scr[p * 512 + tid];
            g_vc[(b * TMS + i) * DD + tid] = s;
        }
        __syncthreads();

        // ---- attention scores sc[h][t] (t<=i), float4 dots ----
        if (tid < HH * (i + 1)) {
            int t = tid >> 3, h = tid & 7;
            const float4* kp = (const float4*)&g_kc[(b * TMS + t) * DD + h * 64];
            const float4* qp = (const float4*)&s_q[h * 64];
            float acc = 0.0f;
#pragma unroll
            for (int d = 0; d < 16; d++) {
                float4 a = qp[d], k4 = kp[d];
                acc += a.x * k4.x + a.y * k4.y + a.z * k4.z + a.w * k4.w;
            }
            s_sc[h * 64 + t] = acc * 0.125f;
        }
        __syncthreads();

        // ---- per-head softmax over t<=i ----
        if (tid < HH) {
            int h = tid;
            float mx = -INFINITY;
            for (int t = 0; t <= i; t++) mx = fmaxf(mx, s_sc[h * 64 + t]);
            float sm = 0.0f;
            for (int t = 0; t <= i; t++) { float e = expf(s_sc[h * 64 + t] - mx); s_sc[h * 64 + t] = e; sm += e; }
            for (int t = 0; t <= i; t++) s_sc[h * 64 + t] /= sm;
        }
        __syncthreads();

        // ---- ctx ----
        if (tid < DD) {
            int h = tid >> 6;
            float acc = 0.0f;
            for (int t = 0; t <= i; t++) acc += s_sc[h * 64 + t] * g_vc[(b * TMS + t) * DD + tid];
            s_ctx[tid] = acc;
        }
        __syncthreads();

        // ---- x1 = LN1(md + ctx@wo + wo_b) ----
        GEMV_PANEL(wo, s_ctx, 512, 8, 64)
        {
            float val = 0.0f;
            if (tid < DD) {
                float s = wo_b[tid];
#pragma unroll
                for (int p = 0; p < 8; p++) s += s_scr[p * 512 + tid];
                val = s_md[tid] + s;
            }
            float mean = blockSum(tid < DD ? val : 0.0f, rs) / (float)DD;
            float dv = (tid < DD) ? (val - mean) : 0.0f;
            float var = blockSum(dv * dv, rs) / (float)DD;
            if (tid < DD) s_x1[tid] = dv / sqrtf(var + 1e-5f) * ln1_s[tid] + ln1_b[tid];
        }
        __syncthreads();

        // ---- h1 = relu(x1 @ ff1_w + ff1_b): N=2048,K=512,P=2,KC=256 ----
        GEMV_PANEL(ff1_w, s_x1, 2048, 2, 256)
#pragma unroll
        for (int r = 0; r < 2; r++) {
            int n = tid + r * 1024;
            float v = s_scr[n] + s_scr[2048 + n] + ff1_b[n];
            s_h1[n] = fmaxf(v, 0.0f);
        }
        __syncthreads();

        // ---- inten = LN2(x1 + h1 @ ff2_w + ff2_b): N=512,K=2048,P=8,KC=256 ----
        GEMV_PANEL(ff2_w, s_h1, 512, 8, 256)
        {
            float val = 0.0f;
            if (tid < DD) {
                float s = ff2_b[tid];
#pragma unroll
                for (int p = 0; p < 8; p++) s += s_scr[p * 512 + tid];
                val = s_x1[tid] + s;
            }
            float mean = blockSum(tid < DD ? val : 0.0f, rs) / (float)DD;
            float dv = (tid < DD) ? (val - mean) : 0.0f;
            float var = blockSum(dv * dv, rs) / (float)DD;
            if (tid < DD) s_int[tid] = dv / sqrtf(var + 1e-5f) * ln2_s[tid] + ln2_b[tid];
        }
        __syncthreads();

        // ---- new_time, iml ----
        float tdot = blockSum(tid < DD ? s_int[tid] * tl_w[tid] : 0.0f, rs) + tl_b[0];
        float nt = lt + (fmaxf(tdot, 0.0f) + log1pf(expf(-fabsf(tdot))));
        float iml = blockSum(tid < DD ? s_int[tid] * ml_w[EE + tid] : 0.0f, rs);

        // ---- neighbors, nrec, mw ----
        if (tid < SS) {
            s_nb[tid] = g_nlist[lm * SS + tid];
            s_nrec[1 + i * SS + tid] = g_nprob[lm * SS + tid];
        }
        __syncthreads();
        if (tid < SS) {
            float acc = 0.0f;
            const float* ep = &emb[s_nb[tid] * EE];
#pragma unroll 8
            for (int e = 0; e < EE; e++) acc += ep[e] * ml_w[e];
            s_mw[tid] = acc + iml + ml_b[0];
        }
        __syncthreads();
        if (tid < SS) {
            float v = s_mw[tid];
            float mx = v;
#pragma unroll
            for (int o = 16; o > 0; o >>= 1) mx = fmaxf(mx, __shfl_xor_sync(0xffffffffu, mx, o));
            float ex = expf(v - mx);
            float sm = ex;
#pragma unroll
            for (int o = 16; o > 0; o >>= 1) sm += __shfl_xor_sync(0xffffffffu, sm, o);
            float mp = ex / sm;
            float pc = s_prob[chosen];
            __syncwarp();
            float att = pc * mp;
            if (tid == 0) s_prob[chosen] = att;
            else {
                s_prob[1 + i * (SS - 1) + tid - 1] = att;
                s_cand[1 + i * (SS - 1) + tid - 1] = s_nb[tid];
            }
        }
        __syncthreads();

        // ---- categorical with key fold_in(key(11), i) ----
        uint32_t ka, kb;
        tf2x32(0u, 11u, 0u, (uint32_t)i, ka, kb);
        float bv = -INFINITY; int bi = 0x7fffffff;
        for (int j = tid; j < LP; j += 1024) {
            float z = logf(s_prob[j]) + gumbel_u32(rbits(ka, kb, (uint32_t)(b * LP + j)));
            if (z > bv) { bv = z; bi = j; }
        }
        blockArgmax(bv, bi, rv, ri);

        if (tid == 0) {
            int nc = bi;
            int nm = s_cand[nc];
            sv_lm = nm; sv_lt = nt; sv_chosen = nc;
            int o = b * TT + (i + 1);
            out[0 * (BB * TT) + o] = (float)nm;
            out[1 * (BB * TT) + o] = nt;
            out[2 * (BB * TT) + o] = (nt < 50.0f) ? 1.0f : 0.0f;
            out[3 * (BB * TT) + o] = s_nrec[nc];
            out[4 * (BB * TT) + o] = s_prob[nc];
        }
        __syncthreads();
    }
}

extern "C" void kernel_launch(void* const* d_in, const int* in_sizes, int n_in,
                              void* d_out, int out_size) {
    const int*   marker = (const int*)  d_in[0];
    const float* timed  = (const float*)d_in[1];
    const float* maskd  = (const float*)d_in[2];
    const float* emb    = (const float*)d_in[3];
    const float* te_w   = (const float*)d_in[4];
    const float* te_b   = (const float*)d_in[5];
    const float* el_w   = (const float*)d_in[6];
    const float* el_b   = (const float*)d_in[7];
    const float* s1_w   = (const float*)d_in[8];
    const float* s1_b   = (const float*)d_in[9];
    const float* s2_w   = (const float*)d_in[10];
    const float* s2_b   = (const float*)d_in[11];
    const float* ml_w   = (const float*)d_in[12];
    const float* ml_b   = (const float*)d_in[13];
    const float* tl_w   = (const float*)d_in[14];
    const float* tl_b   = (const float*)d_in[15];
    const float* wq     = (const float*)d_in[16];
    const float* wk     = (const float*)d_in[17];
    const float* wv     = (const float*)d_in[18];
    const float* wo     = (const float*)d_in[19];
    const float* wo_b   = (const float*)d_in[20];
    const float* ln1_s  = (const float*)d_in[21];
    const float* ln1_b  = (const float*)d_in[22];
    const float* ff1_w  = (const float*)d_in[23];
    const float* ff1_b  = (const float*)d_in[24];
    const float* ff2_w  = (const float*)d_in[25];
    const float* ff2_b  = (const float*)d_in[26];
    const float* ln2_s  = (const float*)d_in[27];
    const float* ln2_b  = (const float*)d_in[28];
    float* out = (float*)d_out;

    static int smem_set = 0;
    if (!smem_set) {
        cudaFuncSetAttribute(k_seq, cudaFuncAttributeMaxDynamicSharedMemorySize,
                             SMEM_SEQ_BYTES);
        smem_set = 1;
    }

    k_topk_cand<<<1, 1024>>>();
    k_bm<<<MM, EE>>>(emb, s1_w);
    k_a<<<CC, EE>>>(emb, s1_w);
    k_select<<<MM, CC>>>(s1_b, s2_w, s2_b);
    k_seq<<<BB, 1024, SMEM_SEQ_BYTES>>>(marker, timed, maskd, emb, te_w, te_b,
                        el_w, el_b, ml_w, ml_b, tl_w, tl_b, wq, wk, wv, wo, wo_b,
                        ln1_s, ln1_b, ff1_w, ff1_b, ff2_w, ff2_b, ln2_s, ln2_b,
                        out);
}